// round 13
// baseline (speedup 1.0000x reference)
#include <cuda_runtime.h>
#include <cuda_fp16.h>
#include <mma.h>
using namespace nvcuda;

#define BSZ  4
#define NDIM 512
#define HDIM 128
#define NJ   10                  // sine-basis terms
#define KP   (HDIM * 2 * NJ)     // 2560 f16 inner dim
#define KPU  (KP / 2)            // 1280 u32 per row
#define OMEGA0 0.2855993321f     // pi / (2 * 5.5)
#define LFIT 5.5f

// ---------------- device scratch (no allocs allowed) ----------------
__device__ float    g_beta[NJ];
__device__ unsigned gF_A[BSZ * NDIM * KPU];   // [b*512+n][p]  p = k*NJ + j: (sin, cos)
__device__ unsigned gF_C[BSZ * NDIM * KPU];   // [b*512+m][p]: (bw*cos, bw*sin)

// ---------------- kernel 0: Fourier coefficients (Galerkin, trapezoid) ------
__global__ void setup_kernel() {
    int j = threadIdx.x >> 5, lane = threadIdx.x & 31;
    if (j >= NJ) return;
    const int NPT = 1024;
    const float h = LFIT / NPT;
    const float om = (2 * j + 1) * OMEGA0;
    float s = 0.f;
    for (int i = lane + 1; i <= NPT; i += 32) {
        float x = i * h;
        float wgt = (i == NPT) ? 0.5f : 1.0f;
        s += wgt * tanhf(x) * sinf(om * x);
    }
#pragma unroll
    for (int o = 16; o; o >>= 1) s += __shfl_xor_sync(0xffffffffu, s, o);
    if (lane == 0) g_beta[j] = s * h * 2.0f / LFIT;
}

// ---------------- kernel 1: projection GEMM -> sin/cos f16 features ---------
// GEMM part identical to prior rounds; epilogue stages a/c into smem then
// emits per (k,j): A half -> (sin, cos); C half -> (beta_j*w_k*cos, *sin).
__global__ __launch_bounds__(256) void proj_feat_kernel(
    const float* __restrict__ first,
    const float* __restrict__ second,
    const float4* __restrict__ Wc4,     // W_concat float4, row stride 64
    const float* __restrict__ bias,     // b_concat
    const float* __restrict__ Wsingle)  // W_single[0][:]
{
    __shared__ __align__(16) char smraw[34816];
    float4* WsE = (float4*)smraw;                  // 64*17 float4
    float4* WsO = (float4*)(smraw + 17408);
    float*  sa  = (float*)smraw;                   // [32][132] (aliases Ws after use)
    __shared__ float wsm[HDIM];
    __shared__ float gb[NJ];

    const int half = blockIdx.y;
    const float4* __restrict__ X4 = (const float4*)(half ? second : first);

    const int row0 = blockIdx.x * 32;
    const int tid  = threadIdx.x;
    const int warp = tid >> 5;
    const int lane = tid & 31;

    if (tid < HDIM) wsm[tid] = Wsingle[tid];
    if (tid < NJ)   gb[tid]  = g_beta[tid];

    float acc[4][4];
#pragma unroll
    for (int r = 0; r < 4; ++r)
#pragma unroll
        for (int g = 0; g < 4; ++g) acc[r][g] = 0.f;

#pragma unroll
    for (int chunk = 0; chunk < 2; ++chunk) {
        if (chunk) __syncthreads();
#pragma unroll
        for (int it = 0; it < 8; ++it) {
            int idx = tid + it * 256;
            int col = idx >> 4;
            int f   = idx & 15;
            float4 v = Wc4[col * 64 + half * 32 + chunk * 16 + f];
            if (col & 1) WsO[(col >> 1) * 17 + f] = v;
            else         WsE[(col >> 1) * 17 + f] = v;
        }
        __syncthreads();

#pragma unroll
        for (int f = 0; f < 16; ++f) {
            float4 w4[4];
            w4[0] = WsE[lane * 17 + f];
            w4[1] = WsO[lane * 17 + f];
            w4[2] = WsE[(lane + 32) * 17 + f];
            w4[3] = WsO[(lane + 32) * 17 + f];
#pragma unroll
            for (int r = 0; r < 4; ++r) {
                float4 x = X4[(row0 + warp * 4 + r) * 32 + chunk * 16 + f];
#pragma unroll
                for (int g = 0; g < 4; ++g) {
                    acc[r][g] = fmaf(x.x, w4[g].x, acc[r][g]);
                    acc[r][g] = fmaf(x.y, w4[g].y, acc[r][g]);
                    acc[r][g] = fmaf(x.z, w4[g].z, acc[r][g]);
                    acc[r][g] = fmaf(x.w, w4[g].w, acc[r][g]);
                }
            }
        }
    }

    float b0 = 0.f, b1 = 0.f, b2 = 0.f, b3 = 0.f;
    if (half == 0) {                 // fold b_concat into a (inside tanh arg)
        b0 = bias[2 * lane];      b1 = bias[2 * lane + 1];
        b2 = bias[2 * lane + 64]; b3 = bias[2 * lane + 65];
    }

    __syncthreads();                 // Ws tiles dead; reuse as sa
#pragma unroll
    for (int r = 0; r < 4; ++r) {
        int rl = warp * 4 + r;
        sa[rl * 132 + 2 * lane]      = acc[r][0] + b0;
        sa[rl * 132 + 2 * lane + 1]  = acc[r][1] + b1;
        sa[rl * 132 + 2 * lane + 64] = acc[r][2] + b2;
        sa[rl * 132 + 2 * lane + 65] = acc[r][3] + b3;
    }
    __syncthreads();

    unsigned* __restrict__ dst = half ? gF_C : gF_A;
    for (int r = 0; r < 32; ++r) {
        const float* sr = &sa[r * 132];
        unsigned* drow = dst + (size_t)(row0 + r) * KPU;
#pragma unroll
        for (int it = 0; it < KPU / 256; ++it) {     // 5
            int p = tid + it * 256;                  // 0..1279
            int k = p / NJ;
            int j = p - k * NJ;
            float s = sr[k];
            float sn, cs;
            __sincosf((2 * j + 1) * OMEGA0 * s, &sn, &cs);
            __half2 hv;
            if (half == 0) hv = __floats2half2_rn(sn, cs);
            else {
                float sc = gb[j] * wsm[k];
                hv = __floats2half2_rn(cs * sc, sn * sc);
            }
            drow[p] = *(unsigned*)&hv;
        }
    }
}

// ---------------- kernel 2: tensor-core GEMM  out = F_A x F_C^T + bias ------
__global__ __launch_bounds__(256) void gemm_kernel(
    const float* __restrict__ bsingle,
    float* __restrict__ out)
{
    __shared__ __align__(16) __half As[2][64][80];
    __shared__ __align__(16) __half Bs[2][64][80];

    const int b  = blockIdx.z;
    const int n0 = blockIdx.x * 64;
    const int m0 = blockIdx.y * 64;
    const int t  = threadIdx.x;
    const int w  = t >> 5;
    const int wn = w & 1;           // 0..1 : n-subtile (32 rows)
    const int wm = w >> 1;          // 0..3 : m-subtile (16 cols)

    const uint4* FA = (const uint4*)gF_A + (size_t)(b * NDIM + n0) * (KPU / 4);
    const uint4* FB = (const uint4*)gF_C + (size_t)(b * NDIM + m0) * (KPU / 4);

    const int i0 = t * 2, i1 = t * 2 + 1;
    const int r_0 = i0 >> 3, q_0 = i0 & 7;
    const int r_1 = i1 >> 3, q_1 = i1 & 7;
    uint4* Au4 = (uint4*)&As[0][0][0];    // row stride 10 uint4 per [64][80] buf
    uint4* Bu4 = (uint4*)&Bs[0][0][0];

    wmma::fragment<wmma::accumulator, 16, 16, 16, float> accf[2];
    wmma::fill_fragment(accf[0], 0.0f);
    wmma::fill_fragment(accf[1], 0.0f);

    // chunk 0 load
    uint4 ra0 = FA[r_0 * (KPU / 4) + q_0], ra1 = FA[r_1 * (KPU / 4) + q_1];
    uint4 rb0 = FB[r_0 * (KPU / 4) + q_0], rb1 = FB[r_1 * (KPU / 4) + q_1];
    Au4[r_0 * 10 + q_0] = ra0;  Au4[r_1 * 10 + q_1] = ra1;
    Bu4[r_0 * 10 + q_0] = rb0;  Bu4[r_1 * 10 + q_1] = rb1;
    __syncthreads();

    int d = 0;
    const int NCH = KP / 64;              // 40
    for (int c = 0; c < NCH; ++c) {
        if (c + 1 < NCH) {                // prefetch next chunk
            ra0 = FA[r_0 * (KPU / 4) + (c + 1) * 8 + q_0];
            ra1 = FA[r_1 * (KPU / 4) + (c + 1) * 8 + q_1];
            rb0 = FB[r_0 * (KPU / 4) + (c + 1) * 8 + q_0];
            rb1 = FB[r_1 * (KPU / 4) + (c + 1) * 8 + q_1];
        }
#pragma unroll
        for (int ks = 0; ks < 4; ++ks) {
            wmma::fragment<wmma::matrix_b, 16, 16, 16, __half, wmma::col_major> bf;
            wmma::load_matrix_sync(bf, &Bs[d][wm * 16][ks * 16], 80);
#pragma unroll
            for (int f = 0; f < 2; ++f) {
                wmma::fragment<wmma::matrix_a, 16, 16, 16, __half, wmma::row_major> af;
                wmma::load_matrix_sync(af, &As[d][wn * 32 + f * 16][ks * 16], 80);
                wmma::mma_sync(accf[f], af, bf, accf[f]);
            }
        }
        if (c + 1 < NCH) {
            int dn = d ^ 1;
            uint4* Adst = (uint4*)&As[dn][0][0];
            uint4* Bdst = (uint4*)&Bs[dn][0][0];
            Adst[r_0 * 10 + q_0] = ra0;  Adst[r_1 * 10 + q_1] = ra1;
            Bdst[r_0 * 10 + q_0] = rb0;  Bdst[r_1 * 10 + q_1] = rb1;
            __syncthreads();
            d = dn;
        }
    }

    const float bs = bsingle[0];
#pragma unroll
    for (int f = 0; f < 2; ++f) {
#pragma unroll
        for (int e = 0; e < accf[f].num_elements; ++e) accf[f].x[e] += bs;
        float* op = out + ((size_t)b * NDIM + n0 + wn * 32 + f * 16) * 512 + m0 + wm * 16;
        wmma::store_matrix_sync(op, accf[f], 512, wmma::mem_row_major);
    }
}

// ---------------- launch ----------------
extern "C" void kernel_launch(void* const* d_in, const int* in_sizes, int n_in,
                              void* d_out, int out_size) {
    const float* first   = (const float*)d_in[0];
    const float* second  = (const float*)d_in[1];
    const float* Wconcat = (const float*)d_in[2];
    const float* bconcat = (const float*)d_in[3];
    const float* Wsingle = (const float*)d_in[4];
    const float* bsingle = (const float*)d_in[5];
    float* out = (float*)d_out;

    setup_kernel<<<1, 320>>>();
    proj_feat_kernel<<<dim3(2048 / 32, 2), 256>>>(first, second, (const float4*)Wconcat,
                                                  bconcat, Wsingle);
    gemm_kernel<<<dim3(8, 8, BSZ), 256>>>(bsingle, out);
}

// round 14
// speedup vs baseline: 1.0884x; 1.0884x over previous
#include <cuda_runtime.h>
#include <cuda_fp16.h>
#include <mma.h>
using namespace nvcuda;

#define BSZ  4
#define NDIM 512
#define HDIM 128
#define NJ   10                  // sine-basis terms
#define KP   (HDIM * 2 * NJ)     // 2560 f16 inner dim
#define KPU  (KP / 2)            // 1280 u32 per row; layout p = j*128 + k
#define OMEGA0 0.2855993321f     // pi / (2 * 5.5)
#define LFIT 5.5f

// ---------------- device scratch (no allocs allowed) ----------------
__device__ float    g_beta[NJ];
__device__ unsigned gF_A[BSZ * NDIM * KPU];   // [b*512+n][j*128+k]: (sin, cos)
__device__ unsigned gF_C[BSZ * NDIM * KPU];   // [b*512+m][j*128+k]: (bw*cos, bw*sin)

// ---------------- kernel 0: Fourier coefficients (Galerkin, trapezoid) ------
__global__ void setup_kernel() {
    __shared__ float red[128];
    const int j = blockIdx.x;
    const int t = threadIdx.x;
    const int NPT = 1024;
    const float h = LFIT / NPT;
    const float om = (2 * j + 1) * OMEGA0;
    float s = 0.f;
    for (int i = t + 1; i <= NPT; i += 128) {
        float x = i * h;
        float wgt = (i == NPT) ? 0.5f : 1.0f;
        s += wgt * tanhf(x) * sinf(om * x);
    }
    red[t] = s;
    __syncthreads();
    for (int o = 64; o; o >>= 1) {
        if (t < o) red[t] += red[t + o];
        __syncthreads();
    }
    if (t == 0) g_beta[j] = red[0] * h * 2.0f / LFIT;
}

// ---------------- kernel 1: projection GEMM -> sin/cos f16 features ---------
// GEMM identical to prior rounds; epilogue: ONE sincos per (row,k), then
// complex recurrence over j (4 FMA per term). Coalesced stores (k = lane).
__global__ __launch_bounds__(256) void proj_feat_kernel(
    const float* __restrict__ first,
    const float* __restrict__ second,
    const float4* __restrict__ Wc4,     // W_concat float4, row stride 64
    const float* __restrict__ bias,     // b_concat
    const float* __restrict__ Wsingle)  // W_single[0][:]
{
    __shared__ __align__(16) char smraw[34816];
    float4* WsE = (float4*)smraw;                  // 64*17 float4
    float4* WsO = (float4*)(smraw + 17408);
    float*  sa  = (float*)smraw;                   // [32][132] (aliases Ws after use)
    __shared__ float wsm[HDIM];
    __shared__ float gb[NJ];

    const int half = blockIdx.y;
    const float4* __restrict__ X4 = (const float4*)(half ? second : first);

    const int row0 = blockIdx.x * 32;
    const int tid  = threadIdx.x;
    const int warp = tid >> 5;
    const int lane = tid & 31;

    if (tid < HDIM) wsm[tid] = Wsingle[tid];
    if (tid < NJ)   gb[tid]  = g_beta[tid];

    float acc[4][4];
#pragma unroll
    for (int r = 0; r < 4; ++r)
#pragma unroll
        for (int g = 0; g < 4; ++g) acc[r][g] = 0.f;

#pragma unroll
    for (int chunk = 0; chunk < 2; ++chunk) {
        if (chunk) __syncthreads();
#pragma unroll
        for (int it = 0; it < 8; ++it) {
            int idx = tid + it * 256;
            int col = idx >> 4;
            int f   = idx & 15;
            float4 v = Wc4[col * 64 + half * 32 + chunk * 16 + f];
            if (col & 1) WsO[(col >> 1) * 17 + f] = v;
            else         WsE[(col >> 1) * 17 + f] = v;
        }
        __syncthreads();

#pragma unroll
        for (int f = 0; f < 16; ++f) {
            float4 w4[4];
            w4[0] = WsE[lane * 17 + f];
            w4[1] = WsO[lane * 17 + f];
            w4[2] = WsE[(lane + 32) * 17 + f];
            w4[3] = WsO[(lane + 32) * 17 + f];
#pragma unroll
            for (int r = 0; r < 4; ++r) {
                float4 x = X4[(row0 + warp * 4 + r) * 32 + chunk * 16 + f];
#pragma unroll
                for (int g = 0; g < 4; ++g) {
                    acc[r][g] = fmaf(x.x, w4[g].x, acc[r][g]);
                    acc[r][g] = fmaf(x.y, w4[g].y, acc[r][g]);
                    acc[r][g] = fmaf(x.z, w4[g].z, acc[r][g]);
                    acc[r][g] = fmaf(x.w, w4[g].w, acc[r][g]);
                }
            }
        }
    }

    float b0 = 0.f, b1 = 0.f, b2 = 0.f, b3 = 0.f;
    if (half == 0) {                 // fold b_concat into a (inside tanh arg)
        b0 = bias[2 * lane];      b1 = bias[2 * lane + 1];
        b2 = bias[2 * lane + 64]; b3 = bias[2 * lane + 65];
    }

    __syncthreads();                 // Ws tiles dead; reuse as sa
#pragma unroll
    for (int r = 0; r < 4; ++r) {
        int rl = warp * 4 + r;
        sa[rl * 132 + 2 * lane]      = acc[r][0] + b0;
        sa[rl * 132 + 2 * lane + 1]  = acc[r][1] + b1;
        sa[rl * 132 + 2 * lane + 64] = acc[r][2] + b2;
        sa[rl * 132 + 2 * lane + 65] = acc[r][3] + b3;
    }
    __syncthreads();

    unsigned* __restrict__ dst = half ? gF_C : gF_A;
    const int kk = tid & 127;        // feature k  (lane-consecutive -> coalesced)
    const int rh = tid >> 7;         // row half (0/1)
    const float wk = wsm[kk];

#pragma unroll 2
    for (int rr = 0; rr < 16; ++rr) {
        const int r = 2 * rr + rh;
        const float s = sa[r * 132 + kk];
        float sj, cj;
        __sincosf(OMEGA0 * s, &sj, &cj);          // base angle (only sincos!)
        const float sd = 2.f * sj * cj;           // double angle
        const float cd = fmaf(2.f * cj, cj, -1.f);
        unsigned* drow = dst + (size_t)(row0 + r) * KPU;
        if (half == 0) {
#pragma unroll
            for (int j = 0; j < NJ; ++j) {
                __half2 hv = __floats2half2_rn(sj, cj);
                drow[j * 128 + kk] = *(unsigned*)&hv;
                float ns = fmaf(sj, cd, cj * sd);
                float nc = fmaf(cj, cd, -sj * sd);
                sj = ns; cj = nc;
            }
        } else {
#pragma unroll
            for (int j = 0; j < NJ; ++j) {
                float sc = gb[j] * wk;
                __half2 hv = __floats2half2_rn(cj * sc, sj * sc);
                drow[j * 128 + kk] = *(unsigned*)&hv;
                float ns = fmaf(sj, cd, cj * sd);
                float nc = fmaf(cj, cd, -sj * sd);
                sj = ns; cj = nc;
            }
        }
    }
}

// ---------------- kernel 2: tensor-core GEMM  out = F_A x F_C^T + bias ------
__global__ __launch_bounds__(256) void gemm_kernel(
    const float* __restrict__ bsingle,
    float* __restrict__ out)
{
    __shared__ __align__(16) __half As[2][64][80];
    __shared__ __align__(16) __half Bs[2][64][80];

    const int b  = blockIdx.z;
    const int n0 = blockIdx.x * 64;
    const int m0 = blockIdx.y * 64;
    const int t  = threadIdx.x;
    const int w  = t >> 5;
    const int wn = w & 1;           // 0..1 : n-subtile (32 rows)
    const int wm = w >> 1;          // 0..3 : m-subtile (16 cols)

    const uint4* FA = (const uint4*)gF_A + (size_t)(b * NDIM + n0) * (KPU / 4);
    const uint4* FB = (const uint4*)gF_C + (size_t)(b * NDIM + m0) * (KPU / 4);

    const int i0 = t * 2, i1 = t * 2 + 1;
    const int r_0 = i0 >> 3, q_0 = i0 & 7;
    const int r_1 = i1 >> 3, q_1 = i1 & 7;
    uint4* Au4 = (uint4*)&As[0][0][0];    // row stride 10 uint4 per [64][80] buf
    uint4* Bu4 = (uint4*)&Bs[0][0][0];

    wmma::fragment<wmma::accumulator, 16, 16, 16, float> accf[2];
    wmma::fill_fragment(accf[0], 0.0f);
    wmma::fill_fragment(accf[1], 0.0f);

    // chunk 0 load
    uint4 ra0 = FA[r_0 * (KPU / 4) + q_0], ra1 = FA[r_1 * (KPU / 4) + q_1];
    uint4 rb0 = FB[r_0 * (KPU / 4) + q_0], rb1 = FB[r_1 * (KPU / 4) + q_1];
    Au4[r_0 * 10 + q_0] = ra0;  Au4[r_1 * 10 + q_1] = ra1;
    Bu4[r_0 * 10 + q_0] = rb0;  Bu4[r_1 * 10 + q_1] = rb1;
    __syncthreads();

    int d = 0;
    const int NCH = KP / 64;              // 40
    for (int c = 0; c < NCH; ++c) {
        if (c + 1 < NCH) {                // prefetch next chunk
            ra0 = FA[r_0 * (KPU / 4) + (c + 1) * 8 + q_0];
            ra1 = FA[r_1 * (KPU / 4) + (c + 1) * 8 + q_1];
            rb0 = FB[r_0 * (KPU / 4) + (c + 1) * 8 + q_0];
            rb1 = FB[r_1 * (KPU / 4) + (c + 1) * 8 + q_1];
        }
#pragma unroll
        for (int ks = 0; ks < 4; ++ks) {
            wmma::fragment<wmma::matrix_b, 16, 16, 16, __half, wmma::col_major> bf;
            wmma::load_matrix_sync(bf, &Bs[d][wm * 16][ks * 16], 80);
#pragma unroll
            for (int f = 0; f < 2; ++f) {
                wmma::fragment<wmma::matrix_a, 16, 16, 16, __half, wmma::row_major> af;
                wmma::load_matrix_sync(af, &As[d][wn * 32 + f * 16][ks * 16], 80);
                wmma::mma_sync(accf[f], af, bf, accf[f]);
            }
        }
        if (c + 1 < NCH) {
            int dn = d ^ 1;
            uint4* Adst = (uint4*)&As[dn][0][0];
            uint4* Bdst = (uint4*)&Bs[dn][0][0];
            Adst[r_0 * 10 + q_0] = ra0;  Adst[r_1 * 10 + q_1] = ra1;
            Bdst[r_0 * 10 + q_0] = rb0;  Bdst[r_1 * 10 + q_1] = rb1;
            __syncthreads();
            d = dn;
        }
    }

    const float bs = bsingle[0];
#pragma unroll
    for (int f = 0; f < 2; ++f) {
#pragma unroll
        for (int e = 0; e < accf[f].num_elements; ++e) accf[f].x[e] += bs;
        float* op = out + ((size_t)b * NDIM + n0 + wn * 32 + f * 16) * 512 + m0 + wm * 16;
        wmma::store_matrix_sync(op, accf[f], 512, wmma::mem_row_major);
    }
}

// ---------------- launch ----------------
extern "C" void kernel_launch(void* const* d_in, const int* in_sizes, int n_in,
                              void* d_out, int out_size) {
    const float* first   = (const float*)d_in[0];
    const float* second  = (const float*)d_in[1];
    const float* Wconcat = (const float*)d_in[2];
    const float* bconcat = (const float*)d_in[3];
    const float* Wsingle = (const float*)d_in[4];
    const float* bsingle = (const float*)d_in[5];
    float* out = (float*)d_out;

    setup_kernel<<<NJ, 128>>>();
    proj_feat_kernel<<<dim3(2048 / 32, 2), 256>>>(first, second, (const float4*)Wconcat,
                                                  bconcat, Wsingle);
    gemm_kernel<<<dim3(8, 8, BSZ), 256>>>(bsingle, out);
}

// round 15
// speedup vs baseline: 2.3868x; 2.1930x over previous
#include <cuda_runtime.h>
#include <cuda_fp16.h>

#define BSZ  4
#define NDIM 512
#define MDIM 512
#define HDIM 128
#define K2   (HDIM / 2)   // 64 half2 per row

// ---------------- device scratch (no allocs allowed) ----------------
// Half2 slot h: j = h>>2 (uint4 index), s = h&3.
// Routing: j even -> slot s==3 pre-tanh'd; j odd -> slots s>=2 pre-tanh'd.
// (5/8 raw -> MUFU tanh in score kernel; 3/8 pre-tanh'd -> identity path)
__device__ __half2 gh_A[BSZ * NDIM * K2];
__device__ __half2 gh_C[BSZ * MDIM * K2];

__device__ __forceinline__ float ftanh(float x) {
    float y;
    asm("tanh.approx.f32 %0, %1;" : "=f"(y) : "f"(x));
    return y;
}

// ---------------- kernel 1: projection GEMM -> routed half2 output ----------
__global__ __launch_bounds__(256) void proj_kernel(
    const float* __restrict__ first,
    const float* __restrict__ second,
    const float4* __restrict__ Wc4,   // W_concat as float4, row stride 64
    const float* __restrict__ bias)   // b_concat
{
    __shared__ float4 WsE[64 * 17];   // even cols: [p][f(16)+pad]
    __shared__ float4 WsO[64 * 17];   // odd  cols

    const int half = blockIdx.y;
    const float4* __restrict__ X4 = (const float4*)(half ? second : first);
    __half2* __restrict__ Out = half ? gh_C : gh_A;

    const int row0 = blockIdx.x * 32;
    const int tid  = threadIdx.x;
    const int warp = tid >> 5;
    const int lane = tid & 31;

    float acc[4][4];
#pragma unroll
    for (int r = 0; r < 4; ++r)
#pragma unroll
        for (int g = 0; g < 4; ++g) acc[r][g] = 0.f;

#pragma unroll
    for (int chunk = 0; chunk < 2; ++chunk) {
        if (chunk) __syncthreads();
#pragma unroll
        for (int it = 0; it < 8; ++it) {
            int idx = tid + it * 256;          // 0..2047
            int col = idx >> 4;
            int f   = idx & 15;
            float4 v = Wc4[col * 64 + half * 32 + chunk * 16 + f];
            if (col & 1) WsO[(col >> 1) * 17 + f] = v;
            else         WsE[(col >> 1) * 17 + f] = v;
        }
        __syncthreads();

#pragma unroll
        for (int f = 0; f < 16; ++f) {
            float4 w4[4];
            w4[0] = WsE[lane * 17 + f];          // col 2l
            w4[1] = WsO[lane * 17 + f];          // col 2l+1
            w4[2] = WsE[(lane + 32) * 17 + f];   // col 2l+64
            w4[3] = WsO[(lane + 32) * 17 + f];   // col 2l+65
#pragma unroll
            for (int r = 0; r < 4; ++r) {
                float4 x = X4[(row0 + warp * 4 + r) * 32 + chunk * 16 + f];
#pragma unroll
                for (int g = 0; g < 4; ++g) {
                    acc[r][g] = fmaf(x.x, w4[g].x, acc[r][g]);
                    acc[r][g] = fmaf(x.y, w4[g].y, acc[r][g]);
                    acc[r][g] = fmaf(x.z, w4[g].z, acc[r][g]);
                    acc[r][g] = fmaf(x.w, w4[g].w, acc[r][g]);
                }
            }
        }
    }

    float b0 = 0.f, b1 = 0.f, b2 = 0.f, b3 = 0.f;
    if (half == 0) {                 // fold b_concat into A
        b0 = bias[2 * lane];      b1 = bias[2 * lane + 1];
        b2 = bias[2 * lane + 64]; b3 = bias[2 * lane + 65];
    }

    // routing flag: h1 = lane, h2 = lane+32 -> same (j parity, s)
    const int j = lane >> 2, s = lane & 3;
    const bool tflag = (j & 1) ? (s >= 2) : (s == 3);
    const float CL = 0.9990234375f;  // 1 - 2^-10  (keeps denom >= 0.00195)

#pragma unroll
    for (int r = 0; r < 4; ++r) {
        int row = row0 + warp * 4 + r;
        float v0 = acc[r][0] + b0, v1 = acc[r][1] + b1;
        float v2 = acc[r][2] + b2, v3 = acc[r][3] + b3;
        if (tflag) {
            v0 = fminf(fmaxf(ftanh(v0), -CL), CL);
            v1 = fminf(fmaxf(ftanh(v1), -CL), CL);
            v2 = fminf(fmaxf(ftanh(v2), -CL), CL);
            v3 = fminf(fmaxf(ftanh(v3), -CL), CL);
        }
        Out[row * K2 + lane]      = __floats2half2_rn(v0, v1);
        Out[row * K2 + 32 + lane] = __floats2half2_rn(v2, v3);
    }
}

// ---------------- identity-path tanh: (ta+tc)/(1+ta*tc), MUFU-free ----------
__device__ __forceinline__ __half2 ident2(__half2 ta, __half2 tc) {
    const unsigned oneu = 0x3C003C00u;
    const __half2 one = *(const __half2*)&oneu;
    __half2 d = __hfma2(ta, tc, one);          // 1 + ta*tc  (>= 0.00195)
    __half2 N = __hadd2(ta, tc);
    unsigned du = *(unsigned*)&d;
    unsigned ndu = du ^ 0x80008000u;           // -d  (LOP3, alu)
    __half2 nd = *(__half2*)&ndu;
    unsigned r0u = 0x78007800u - du;           // rcp guess, err in (-12.5%, 0]
    __half2 R = *(__half2*)&r0u;
    __half2 e = __hfma2(nd, R, one);           // Newton 1
    R = __hfma2(R, e, R);
    e = __hfma2(nd, R, one);                   // Newton 2 (fused into product)
    __half2 t = __hmul2(N, R);
    return __hfma2(t, e, t);                   // N*R*(1+e)
}

// ---------------- kernel 2: fused tanh-score (5/8 MUFU, 3/8 identity) -------
// 128-thread CTAs, 16n x 32m tile: same per-warp inner loop as before, but
// 2048 CTAs @ 10/SM -> smoother waves + higher resident warp count.
__global__ __launch_bounds__(128, 10) void score_kernel(
    const float* __restrict__ Wsingle,
    const float* __restrict__ bsingle,
    float* __restrict__ out)
{
    __shared__ uint4 a4s[16][16];            // [n_local][k2]  (broadcast)
    __shared__ uint4 cs[16][33];             // [k2][m_local]  +1 pad
    __shared__ __align__(16) uint2 wh[32];   // w as half2

    const int b  = blockIdx.z;
    const int n0 = blockIdx.x * 16;
    const int m0 = blockIdx.y * 32;
    const int tid  = threadIdx.x;
    const int warp = tid >> 5;               // 0..3 -> rows warp*4..+3
    const int lane = tid & 31;

    const uint4* __restrict__ A4 = (const uint4*)(gh_A + (size_t)(b * NDIM + n0) * K2);
    const uint4* __restrict__ C4 = (const uint4*)(gh_C + (size_t)(b * MDIM + m0) * K2);

    // stage A-tile: 16 rows x 16 u4 = 256 ; C-tile: 32 rows x 16 u4 = 512
#pragma unroll
    for (int t = 0; t < 2; ++t) {
        int idx = tid + t * 128;             // 0..255
        int i  = idx >> 4;
        int f4 = idx & 15;
        a4s[i][f4] = A4[i * 16 + f4];
    }
#pragma unroll
    for (int t = 0; t < 4; ++t) {
        int idx = tid + t * 128;             // 0..511
        int i  = idx >> 4;                   // m row 0..31
        int f4 = idx & 15;
        cs[f4][i] = C4[i * 16 + f4];
    }
    if (tid < 32) {
        float4 w4 = ((const float4*)Wsingle)[tid];
        __half2 h01 = __floats2half2_rn(w4.x, w4.y);
        __half2 h23 = __floats2half2_rn(w4.z, w4.w);
        wh[tid] = make_uint2(*(unsigned*)&h01, *(unsigned*)&h23);
    }
    __syncthreads();

    float acc0 = 0.f, acc1 = 0.f, acc2 = 0.f, acc3 = 0.f;

#define H2(u) (*(__half2*)&(u))
#define MUFU_T(au_, cu_, out_)                                                \
    {   __half2 s_ = __hadd2(H2(au_), H2(cu_));                               \
        unsigned su_ = *(unsigned*)&s_;                                       \
        asm("tanh.approx.f16x2 %0, %0;" : "+r"(su_));                         \
        out_ = *(__half2*)&su_; }

    // g for one k2 step (no f32 conversion): ODD -> 2 ident slots, else 1
#define STEP_G(AU_, CU_, W0_, W1_, W2_, W3_, ODD, GOUT)                       \
    {   __half2 t0, t1, t2, t3;                                               \
        MUFU_T(AU_.x, CU_.x, t0)                                              \
        MUFU_T(AU_.y, CU_.y, t1)                                              \
        if (ODD) { t2 = ident2(H2(AU_.z), H2(CU_.z)); }                       \
        else     { MUFU_T(AU_.z, CU_.z, t2) }                                 \
        t3 = ident2(H2(AU_.w), H2(CU_.w));                                    \
        GOUT = __hmul2(t0, W0_);                                              \
        GOUT = __hfma2(t1, W1_, GOUT);                                        \
        GOUT = __hfma2(t2, W2_, GOUT);                                        \
        GOUT = __hfma2(t3, W3_, GOUT); }

#pragma unroll 4
    for (int q = 0; q < 8; ++q) {
        const int k0 = 2 * q, k1 = 2 * q + 1;
        const uint4 cu0 = cs[k0][lane];
        const uint4 cu1 = cs[k1][lane];
        const uint4 wu0 = *(const uint4*)&wh[2 * k0];
        const uint4 wu1 = *(const uint4*)&wh[2 * k1];
        const __half2 p0 = H2(wu0.x), p1 = H2(wu0.y), p2 = H2(wu0.z), p3 = H2(wu0.w);
        const __half2 q0 = H2(wu1.x), q1 = H2(wu1.y), q2 = H2(wu1.z), q3 = H2(wu1.w);

#define ROW_PAIR(R_, ACC)                                                     \
        {   uint4 au0 = a4s[warp * 4 + R_][k0];                               \
            uint4 au1 = a4s[warp * 4 + R_][k1];                               \
            __half2 g0, g1;                                                   \
            STEP_G(au0, cu0, p0, p1, p2, p3, false, g0)                       \
            STEP_G(au1, cu1, q0, q1, q2, q3, true,  g1)                       \
            __half2 G = __hadd2(g0, g1);                                      \
            ACC += __low2float(G);                                            \
            ACC += __high2float(G); }

        ROW_PAIR(0, acc0)
        ROW_PAIR(1, acc1)
        ROW_PAIR(2, acc2)
        ROW_PAIR(3, acc3)
#undef ROW_PAIR
    }
#undef STEP_G
#undef MUFU_T
#undef H2

    const float bs = bsingle[0];
    const int nbase = n0 + warp * 4;
    float* __restrict__ op = out + ((size_t)b * NDIM + nbase) * MDIM + m0 + lane;
    op[0 * MDIM] = acc0 + bs;
    op[1 * MDIM] = acc1 + bs;
    op[2 * MDIM] = acc2 + bs;
    op[3 * MDIM] = acc3 + bs;
}

// ---------------- launch ----------------
extern "C" void kernel_launch(void* const* d_in, const int* in_sizes, int n_in,
                              void* d_out, int out_size) {
    const float* first   = (const float*)d_in[0];
    const float* second  = (const float*)d_in[1];
    const float* Wconcat = (const float*)d_in[2];
    const float* bconcat = (const float*)d_in[3];
    const float* Wsingle = (const float*)d_in[4];
    const float* bsingle = (const float*)d_in[5];
    float* out = (float*)d_out;

    proj_kernel<<<dim3(2048 / 32, 2), 256>>>(first, second, (const float4*)Wconcat, bconcat);
    score_kernel<<<dim3(NDIM / 16, MDIM / 32, BSZ), 128>>>(Wsingle, bsingle, out);
}